// round 5
// baseline (speedup 1.0000x reference)
#include <cuda_runtime.h>

#define NIN      2049   // inputs per frame
#define NOUT     1024   // outputs per frame
#define ROWS     12     // frames per CTA -> grid = ceil(1600/12) = 134 (single wave)
#define THREADS  512

__global__ void __launch_bounds__(THREADS)
logscale_kernel(const float* __restrict__ x,
                const float* __restrict__ frac,
                const float* __restrict__ cubt,
                const float* __restrict__ triw,
                const int*   __restrict__ pair,
                const int*   __restrict__ cubi,
                const int*   __restrict__ tridx,
                float* __restrict__ out,
                int n_rows, int n_lin, int n_cub, int max_w)
{
    extern __shared__ float sx[];              // ROWS * NIN floats (96 KB)

    const int row0 = blockIdx.x * ROWS;
    const int nr   = min(ROWS, n_rows - row0);
    const int t    = threadIdx.x;
    const int n_sum = n_lin + n_cub;
    const int n_tri = NOUT - n_sum;
    const float NEG_INF = __int_as_float(0xff800000);

    // ---- Stage nr rows of x into shared memory (coalesced float4) ----
    // row0 multiple of 12; 12*2049 % 4 == 0 -> every CTA chunk 16B-aligned.
    {
        const float* src  = x + (size_t)row0 * NIN;
        const int total   = nr * NIN;
        const int nv      = total >> 2;
        const float4* s4  = (const float4*)src;
        float4* d4        = (float4*)sx;
        for (int i = t; i < nv; i += THREADS) d4[i] = s4[i];
        for (int i = (nv << 2) + t; i < total; i += THREADS) sx[i] = src[i];
    }
    __syncthreads();

    // ================= Phase A: linear + cubic (o in [0, n_sum)) =========
    // Thread t owns columns t and t+512 (only those < n_sum). Uniform cost,
    // coalesced stores.
    #pragma unroll
    for (int half = 0; half < 2; half++) {
        const int o = t + half * THREADS;
        if (o >= n_sum) break;
        if (o < n_lin) {
            const int   i0 = __ldg(pair + o);
            const float f  = __ldg(frac + o);
            #pragma unroll
            for (int r = 0; r < ROWS; r++) {
                const float x0 = sx[r * NIN + i0];
                const float x1 = sx[r * NIN + i0 + 1];
                if (r < nr)
                    out[(size_t)(row0 + r) * NOUT + o] = x0 + f * (x1 - x0);
            }
        } else {
            const int   j  = o - n_lin;
            const int   i0 = __ldg(cubi + j);
            const float tc = __ldg(cubt + j);
            #pragma unroll
            for (int r = 0; r < ROWS; r++) {
                const float* row = sx + r * NIN;
                const float xm1 = row[i0 - 1];
                const float x0  = row[i0];
                const float x1  = row[i0 + 1];
                const float x2  = row[i0 + 2];
                const float v = x0 + 0.5f * tc * (x1 - xm1
                              + tc * (2.0f * xm1 - 5.0f * x0 + 4.0f * x1 - x2
                              + tc * (3.0f * (x0 - x1) + x2 - xm1)));
                if (r < nr)
                    out[(size_t)(row0 + r) * NOUT + o] = v;
            }
        }
    }

    // ================= Phase B: triangular, task = (output j, row r) ======
    // 2736 near-uniform tasks strided over 512 threads. Consecutive task ids
    // share j (12 rows per output), so a warp's lanes span ~3 adjacent j's:
    //   - weight loads broadcast within the warp (same j),
    //   - LDS addresses r*2049 + const hit distinct banks (2049 % 32 == 1),
    //   - per-lane -inf-break lengths are nearly uniform across the warp.
    // Padded triw slots are exactly -inf (valid weights bottom out at -160dB),
    // so -inf is a safe terminator; skipping padding avoids ~2.8x wasted work.
    const int ntask = n_tri * ROWS;
    for (int k = t; k < ntask; k += THREADS) {
        const int j = k / ROWS;
        const int r = k - j * ROWS;
        const int i0 = __ldg(tridx + (size_t)j * max_w);   // first entry always valid
        const float* __restrict__ wp = triw + (size_t)j * max_w;
        const float* __restrict__ p  = sx + r * NIN + i0;

        float m = NEG_INF;
        bool done = false;
        for (int wb = 0; wb < max_w && !done; wb += 4) {
            float wv[4];
            #pragma unroll
            for (int c = 0; c < 4; c++)
                wv[c] = (wb + c < max_w) ? __ldg(wp + wb + c) : NEG_INF;
            #pragma unroll
            for (int c = 0; c < 4; c++) {
                if (__float_as_int(wv[c]) == (int)0xff800000) { done = true; break; }
                m = fmaxf(m, p[wb + c] + wv[c]);
            }
        }
        if (r < nr)
            out[(size_t)(row0 + r) * NOUT + (n_sum + j)] = m;
    }
}

extern "C" void kernel_launch(void* const* d_in, const int* in_sizes, int n_in,
                              void* d_out, int out_size)
{
    const float* x     = (const float*)d_in[0];
    const float* frac  = (const float*)d_in[1];
    const float* cubt  = (const float*)d_in[2];
    const float* triw  = (const float*)d_in[3];
    const int*   pair  = (const int*)d_in[4];
    const int*   cubi  = (const int*)d_in[5];
    const int*   tridx = (const int*)d_in[6];
    float* out = (float*)d_out;

    const int n_lin  = in_sizes[1];
    const int n_cub  = in_sizes[2];
    const int n_tri  = NOUT - n_lin - n_cub;
    const int max_w  = (n_tri > 0) ? in_sizes[3] / n_tri : 0;
    const int n_rows = in_sizes[0] / NIN;

    const int smem = ROWS * NIN * sizeof(float);   // 98352 B -> opt-in
    cudaFuncSetAttribute(logscale_kernel,
                         cudaFuncAttributeMaxDynamicSharedMemorySize, smem);

    const int grid = (n_rows + ROWS - 1) / ROWS;   // 134 CTAs for 1600 rows
    logscale_kernel<<<grid, THREADS, smem>>>(x, frac, cubt, triw,
                                             pair, cubi, tridx, out,
                                             n_rows, n_lin, n_cub, max_w);
}

// round 8
// speedup vs baseline: 1.2122x; 1.2122x over previous
#include <cuda_runtime.h>

#define NIN      2049   // inputs per frame
#define NOUT     1024   // outputs per frame
#define ROWS     12     // frames per CTA -> grid = ceil(1600/12) = 134 (single wave)
#define THREADS  1024   // one output column per thread; 32 warps/SM

__global__ void __launch_bounds__(THREADS)
logscale_kernel(const float* __restrict__ x,
                const float* __restrict__ frac,
                const float* __restrict__ cubt,
                const float* __restrict__ triw,
                const int*   __restrict__ pair,
                const int*   __restrict__ cubi,
                const int*   __restrict__ tridx,
                float* __restrict__ out,
                int n_rows, int n_lin, int n_cub, int max_w, int n_tri)
{
    // Shared layout: sx[ROWS*NIN] | swt[n_tri*(max_w+1)] | si0[n_tri]
    extern __shared__ float smem_pool[];
    float* sx  = smem_pool;
    float* swt = smem_pool + ROWS * NIN;
    int*   si0 = (int*)(swt + n_tri * (max_w + 1));

    const int row0 = blockIdx.x * ROWS;
    const int nr   = min(ROWS, n_rows - row0);
    const int o    = threadIdx.x;              // one output column per thread
    const int n_sum = n_lin + n_cub;
    const int wstride = max_w + 1;             // 41: stride 9 mod 32 -> conflict-free

    // ---- Prologue staging (x tile, tri weights, tri i0s), one sync ----
    {
        // x rows: row0 multiple of 12; 12*2049 % 4 == 0 -> 16B-aligned chunks.
        const float* src  = x + (size_t)row0 * NIN;
        const int total   = nr * NIN;
        const int nv      = total >> 2;
        const float4* s4  = (const float4*)src;
        float4* d4        = (float4*)sx;
        for (int i = o; i < nv; i += THREADS) d4[i] = s4[i];
        for (int i = (nv << 2) + o; i < total; i += THREADS) sx[i] = src[i];

        // tri weights: coalesced global read, padded-stride shared write.
        const int wtot = n_tri * max_w;
        for (int i = o; i < wtot; i += THREADS) {
            const int j = i / max_w;
            const int w = i - j * max_w;
            swt[j * wstride + w] = __ldg(triw + i);
        }
        // tri window starts (first tridx entry of each row is always valid).
        for (int i = o; i < n_tri; i += THREADS)
            si0[i] = __ldg(tridx + (size_t)i * max_w);
    }
    __syncthreads();

    // Warps contiguous in o: coalesced stores; tri window lengths nearly
    // uniform within a warp; heavy tri warps spread 2/SMSP via wid%4.
    if (o < n_lin) {
        // Linear: x0 + f*(x1-x0), x1 at i0+1
        const int   i0 = __ldg(pair + o);
        const float f  = __ldg(frac + o);
        #pragma unroll
        for (int r = 0; r < ROWS; r++) {
            const float x0 = sx[r * NIN + i0];
            const float x1 = sx[r * NIN + i0 + 1];
            if (r < nr)
                out[(size_t)(row0 + r) * NOUT + o] = x0 + f * (x1 - x0);
        }
    } else if (o < n_sum) {
        // Catmull-Rom cubic
        const int   j  = o - n_lin;
        const int   i0 = __ldg(cubi + j);
        const float t  = __ldg(cubt + j);
        #pragma unroll
        for (int r = 0; r < ROWS; r++) {
            const float* row = sx + r * NIN;
            const float xm1 = row[i0 - 1];
            const float x0  = row[i0];
            const float x1  = row[i0 + 1];
            const float x2  = row[i0 + 2];
            const float v = x0 + 0.5f * t * (x1 - xm1
                          + t * (2.0f * xm1 - 5.0f * x0 + 4.0f * x1 - x2
                          + t * (3.0f * (x0 - x1) + x2 - xm1)));
            if (r < nr)
                out[(size_t)(row0 + r) * NOUT + o] = v;
        }
    } else {
        // Triangular: indices contiguous (tridx[j][w] = i0 + w for valid w);
        // padded weights are exactly -inf (valid ones bottom at -160 dB), so
        // -inf is a safe early-exit terminator. 12 independent max chains
        // give ILP; weights now come from conflict-free shared memory.
        const int j  = o - n_sum;
        const int i0 = si0[j];
        const float* __restrict__ wp = swt + j * wstride;
        float m[ROWS];
        #pragma unroll
        for (int r = 0; r < ROWS; r++) m[r] = __int_as_float(0xff800000);

        bool done = false;
        for (int wb = 0; wb < max_w && !done; wb += 4) {
            float wv[4];
            #pragma unroll
            for (int c = 0; c < 4; c++)
                wv[c] = (wb + c < max_w) ? wp[wb + c]
                                         : __int_as_float(0xff800000);
            #pragma unroll
            for (int c = 0; c < 4; c++) {
                if (__float_as_int(wv[c]) == (int)0xff800000) { done = true; break; }
                const float* p = sx + i0 + wb + c;
                #pragma unroll
                for (int r = 0; r < ROWS; r++)
                    m[r] = fmaxf(m[r], p[r * NIN] + wv[c]);
            }
        }
        #pragma unroll
        for (int r = 0; r < ROWS; r++)
            if (r < nr) out[(size_t)(row0 + r) * NOUT + o] = m[r];
    }
}

extern "C" void kernel_launch(void* const* d_in, const int* in_sizes, int n_in,
                              void* d_out, int out_size)
{
    const float* x     = (const float*)d_in[0];
    const float* frac  = (const float*)d_in[1];
    const float* cubt  = (const float*)d_in[2];
    const float* triw  = (const float*)d_in[3];
    const int*   pair  = (const int*)d_in[4];
    const int*   cubi  = (const int*)d_in[5];
    const int*   tridx = (const int*)d_in[6];
    float* out = (float*)d_out;

    const int n_lin  = in_sizes[1];
    const int n_cub  = in_sizes[2];
    const int n_tri  = NOUT - n_lin - n_cub;
    const int max_w  = (n_tri > 0) ? in_sizes[3] / n_tri : 0;
    const int n_rows = in_sizes[0] / NIN;

    // smem: x tile + padded tri weights + tri starts  (~137 KB, opt-in)
    const int smem = (ROWS * NIN + n_tri * (max_w + 1) + n_tri) * (int)sizeof(float);
    cudaFuncSetAttribute(logscale_kernel,
                         cudaFuncAttributeMaxDynamicSharedMemorySize, smem);

    const int grid = (n_rows + ROWS - 1) / ROWS;   // 134 CTAs for 1600 rows
    logscale_kernel<<<grid, THREADS, smem>>>(x, frac, cubt, triw,
                                             pair, cubi, tridx, out,
                                             n_rows, n_lin, n_cub, max_w, n_tri);
}

// round 9
// speedup vs baseline: 1.4177x; 1.1695x over previous
#include <cuda_runtime.h>

#define NIN      2049   // inputs per frame
#define NOUT     1024   // outputs per frame
#define ROWS     12     // frames per CTA -> grid = 134 (single wave)
#define THREADS  1024

__global__ void __launch_bounds__(THREADS)
logscale_kernel(const float* __restrict__ x,
                const float* __restrict__ frac,
                const float* __restrict__ cubt,
                const float* __restrict__ triw,
                const int*   __restrict__ pair,
                const int*   __restrict__ cubi,
                const int*   __restrict__ tridx,
                float* __restrict__ out,
                int n_rows, int n_lin, int n_cub, int max_w, int n_tri)
{
    // Shared: sx[ROWS*NIN] | swt[n_tri*(max_w+1)] | si0[n_tri] | slen[n_tri]
    extern __shared__ float smem_pool[];
    float* sx   = smem_pool;
    float* swt  = smem_pool + ROWS * NIN;
    int*   si0  = (int*)(swt + n_tri * (max_w + 1));
    int*   slen = si0 + n_tri;

    const int row0 = blockIdx.x * ROWS;
    const int nr   = min(ROWS, n_rows - row0);
    const int t    = threadIdx.x;
    const int n_sum   = n_lin + n_cub;
    const int wstride = max_w + 1;             // 41 -> stride 9 mod 32, conflict-free
    const float NEG_INF = __int_as_float(0xff800000);

    // ---- init per-j tri length table ----
    for (int i = t; i < n_tri; i += THREADS) slen[i] = max_w;
    __syncthreads();

    // ---- Staging: x tile (front-batched MLP=6), weights(+len), i0 ----
    {
        const float4* s4 = (const float4*)(x + (size_t)row0 * NIN);
        float4* d4       = (float4*)sx;
        const int nv     = (nr * NIN) >> 2;    // nr*NIN % 4 == 0 (nr in {12,4})
        #pragma unroll
        for (int u = 0; u < 6; u++) {          // 6*1024 = 6144 >= nv except 3 tail
            const int i = t + u * THREADS;
            if (i < nv) d4[i] = s4[i];
        }
        { const int i = t + 6 * THREADS; if (i < nv) d4[i] = s4[i]; }

        // weights: coalesced read, padded-stride write; record first -inf per j
        const int wtot = n_tri * max_w;
        for (int i = t; i < wtot; i += THREADS) {
            const int j = i / max_w;
            const int w = i - j * max_w;
            const float v = __ldg(triw + i);
            swt[j * wstride + w] = v;
            if (__float_as_int(v) == (int)0xff800000) atomicMin(&slen[j], w);
        }
        for (int i = t; i < n_tri; i += THREADS)
            si0[i] = __ldg(tridx + (size_t)i * max_w);  // first entry always valid
    }
    __syncthreads();

    // ================= Triangular: task = (j, row-quarter) ================
    // 4*n_tri = 912 tasks; j DESCENDING in task id so the longest windows go
    // to the lowest threads, which have no Phase-A work. 3 independent max
    // chains per task give ILP; loop trip = exact window length (no branches,
    // no padding work). Weight LDS broadcasts across the 4 lanes sharing j.
    for (int task = t; task < 4 * n_tri; task += THREADS) {
        const int j   = n_tri - 1 - (task >> 2);
        const int q3  = (task & 3) * 3;        // first row of this quarter
        const int i0  = si0[j];
        const int len = slen[j];
        const float* __restrict__ wp = swt + j * wstride;
        const float* __restrict__ p  = sx + q3 * NIN + i0;

        float m0 = NEG_INF, m1 = NEG_INF, m2 = NEG_INF;
        #pragma unroll 4
        for (int w = 0; w < len; w++) {
            const float wg = wp[w];
            m0 = fmaxf(m0, p[w]           + wg);
            m1 = fmaxf(m1, p[NIN + w]     + wg);
            m2 = fmaxf(m2, p[2 * NIN + w] + wg);
        }
        const int o = n_sum + j;
        if (q3 + 0 < nr) out[(size_t)(row0 + q3 + 0) * NOUT + o] = m0;
        if (q3 + 1 < nr) out[(size_t)(row0 + q3 + 1) * NOUT + o] = m1;
        if (q3 + 2 < nr) out[(size_t)(row0 + q3 + 2) * NOUT + o] = m2;
    }

    // ================= Linear + cubic: o = t - (THREADS - n_sum) ==========
    // Highest threads own these columns (low threads carry heavy tri tasks).
    // Warps contiguous in o -> coalesced stores.
    {
        const int o = t - (THREADS - n_sum);
        if (o >= 0) {
            if (o < n_lin) {
                const int   i0 = __ldg(pair + o);
                const float f  = __ldg(frac + o);
                #pragma unroll
                for (int r = 0; r < ROWS; r++) {
                    const float x0 = sx[r * NIN + i0];
                    const float x1 = sx[r * NIN + i0 + 1];
                    if (r < nr)
                        out[(size_t)(row0 + r) * NOUT + o] = x0 + f * (x1 - x0);
                }
            } else {
                const int   j  = o - n_lin;
                const int   i0 = __ldg(cubi + j);
                const float tc = __ldg(cubt + j);
                #pragma unroll
                for (int r = 0; r < ROWS; r++) {
                    const float* row = sx + r * NIN;
                    const float xm1 = row[i0 - 1];
                    const float x0  = row[i0];
                    const float x1  = row[i0 + 1];
                    const float x2  = row[i0 + 2];
                    const float v = x0 + 0.5f * tc * (x1 - xm1
                                  + tc * (2.0f * xm1 - 5.0f * x0 + 4.0f * x1 - x2
                                  + tc * (3.0f * (x0 - x1) + x2 - xm1)));
                    if (r < nr)
                        out[(size_t)(row0 + r) * NOUT + o] = v;
                }
            }
        }
    }
}

extern "C" void kernel_launch(void* const* d_in, const int* in_sizes, int n_in,
                              void* d_out, int out_size)
{
    const float* x     = (const float*)d_in[0];
    const float* frac  = (const float*)d_in[1];
    const float* cubt  = (const float*)d_in[2];
    const float* triw  = (const float*)d_in[3];
    const int*   pair  = (const int*)d_in[4];
    const int*   cubi  = (const int*)d_in[5];
    const int*   tridx = (const int*)d_in[6];
    float* out = (float*)d_out;

    const int n_lin  = in_sizes[1];
    const int n_cub  = in_sizes[2];
    const int n_tri  = NOUT - n_lin - n_cub;
    const int max_w  = (n_tri > 0) ? in_sizes[3] / n_tri : 0;
    const int n_rows = in_sizes[0] / NIN;

    // smem: x tile + padded weights + i0 + len  (~138 KB, opt-in)
    const int smem = (ROWS * NIN + n_tri * (max_w + 1) + 2 * n_tri)
                     * (int)sizeof(float);
    cudaFuncSetAttribute(logscale_kernel,
                         cudaFuncAttributeMaxDynamicSharedMemorySize, smem);

    const int grid = (n_rows + ROWS - 1) / ROWS;   // 134 CTAs for 1600 rows
    logscale_kernel<<<grid, THREADS, smem>>>(x, frac, cubt, triw,
                                             pair, cubi, tridx, out,
                                             n_rows, n_lin, n_cub, max_w, n_tri);
}